// round 1
// baseline (speedup 1.0000x reference)
#include <cuda_runtime.h>

// Sobel |gx|+|gy|+eps over (32,1,1024,1024) f32, SAME zero padding.
// Memory-bound: each thread computes a 4-wide x 16-tall strip with a rolling
// 3-row register window. Coalesced float4 loads/stores.

#define IMG_W 1024
#define IMG_H 1024
#define C4    (IMG_W / 4)   // 256 float4 columns per row
#define RPT   16            // output rows per thread
#define RB    (IMG_H / RPT) // 64 row-blocks per image

__device__ __forceinline__ void load_row6(const float* __restrict__ img,
                                          int r, int c4, float v[6]) {
    if ((unsigned)r >= (unsigned)IMG_H) {
        v[0] = v[1] = v[2] = v[3] = v[4] = v[5] = 0.0f;
        return;
    }
    const float* base = img + (size_t)r * IMG_W + (size_t)c4 * 4;
    float4 ctr = *reinterpret_cast<const float4*>(base);
    v[0] = (c4 > 0)      ? __ldg(base - 1) : 0.0f;
    v[1] = ctr.x; v[2] = ctr.y; v[3] = ctr.z; v[4] = ctr.w;
    v[5] = (c4 < C4 - 1) ? __ldg(base + 4) : 0.0f;
}

__global__ void __launch_bounds__(256)
sobel_grad_kernel(const float* __restrict__ x, float* __restrict__ out) {
    int idx = blockIdx.x * blockDim.x + threadIdx.x;
    int c4 = idx & (C4 - 1);          // float4 column  (0..255)
    int t  = idx >> 8;                // / 256
    int rb = t & (RB - 1);            // row block      (0..63)
    int n  = t >> 6;                  // image index    (0..31)

    const float* img = x   + (size_t)n * IMG_H * IMG_W;
    float*       op  = out + (size_t)n * IMG_H * IMG_W;
    int row0 = rb * RPT;

    float top[6], mid[6], bot[6];
    load_row6(img, row0 - 1, c4, top);
    load_row6(img, row0,     c4, mid);

    #pragma unroll
    for (int i = 0; i < RPT; i++) {
        int r = row0 + i;
        load_row6(img, r + 1, c4, bot);

        float o[4];
        #pragma unroll
        for (int j = 0; j < 4; j++) {
            // window index 0 corresponds to pixel column (4*c4 + j - 1)
            float gx = (top[j + 2] - top[j])
                     + 2.0f * (mid[j + 2] - mid[j])
                     + (bot[j + 2] - bot[j]);
            float gy = (bot[j]     - top[j])
                     + 2.0f * (bot[j + 1] - top[j + 1])
                     + (bot[j + 2] - top[j + 2]);
            o[j] = fabsf(gx) + fabsf(gy) + 1e-5f;
        }
        float4 ov = make_float4(o[0], o[1], o[2], o[3]);
        *reinterpret_cast<float4*>(op + (size_t)r * IMG_W + (size_t)c4 * 4) = ov;

        #pragma unroll
        for (int k = 0; k < 6; k++) { top[k] = mid[k]; mid[k] = bot[k]; }
    }
}

extern "C" void kernel_launch(void* const* d_in, const int* in_sizes, int n_in,
                              void* d_out, int out_size) {
    const float* x = (const float*)d_in[0];
    float* out = (float*)d_out;

    // total pixels / (4 wide * RPT tall) threads, 256 threads per block
    int total_threads = out_size / (4 * RPT);     // 33554432/64 = 524288
    int blocks = (total_threads + 255) / 256;     // 2048
    sobel_grad_kernel<<<blocks, 256>>>(x, out);
}

// round 2
// speedup vs baseline: 1.0048x; 1.0048x over previous
#include <cuda_runtime.h>

// Sobel |gx|+|gy|+eps over (32,1,1024,1024) f32, SAME zero padding.
// Per-thread 4-wide x 16-tall strip, rolling 3-row window + 1-row prefetch.
// Horizontal halo via warp shuffle (only lanes 0/31 do a 1-lane scalar load).

#define IMG_W 1024
#define IMG_H 1024
#define C4    (IMG_W / 4)   // 256 float4 columns per row
#define RPT   16            // output rows per thread
#define RB    (IMG_H / RPT) // 64 row-blocks per image

__device__ __forceinline__ void load_row6(const float* __restrict__ img,
                                          int r, int c4, int lane,
                                          float v[6]) {
    bool in = (unsigned)r < (unsigned)IMG_H;
    const float* base = img + (size_t)r * IMG_W + (size_t)c4 * 4;
    float4 ctr = make_float4(0.f, 0.f, 0.f, 0.f);
    if (in) ctr = *reinterpret_cast<const float4*>(base);

    // neighbor halo via shuffle (all lanes participate)
    float left  = __shfl_up_sync(0xFFFFFFFFu, ctr.w, 1);
    float right = __shfl_down_sync(0xFFFFFFFFu, ctr.x, 1);
    if (lane == 0)
        left  = (in && c4 > 0)      ? __ldg(base - 1) : 0.0f;
    if (lane == 31)
        right = (in && c4 < C4 - 1) ? __ldg(base + 4) : 0.0f;

    v[0] = left;
    v[1] = ctr.x; v[2] = ctr.y; v[3] = ctr.z; v[4] = ctr.w;
    v[5] = right;
}

__global__ void __launch_bounds__(256)
sobel_grad_kernel(const float* __restrict__ x, float* __restrict__ out) {
    int idx  = blockIdx.x * blockDim.x + threadIdx.x;
    int lane = threadIdx.x & 31;
    int c4 = idx & (C4 - 1);          // float4 column  (0..255)
    int t  = idx >> 8;
    int rb = t & (RB - 1);            // row block      (0..63)
    int n  = t >> 6;                  // image index    (0..31)

    const float* img = x   + (size_t)n * IMG_H * IMG_W;
    float*       op  = out + (size_t)n * IMG_H * IMG_W;
    int row0 = rb * RPT;

    float top[6], mid[6], bot[6], nxt[6];
    load_row6(img, row0 - 1, c4, lane, top);
    load_row6(img, row0,     c4, lane, mid);
    load_row6(img, row0 + 1, c4, lane, bot);

    #pragma unroll
    for (int i = 0; i < RPT; i++) {
        int r = row0 + i;

        // prefetch next bottom row (2 ahead of current output row)
        if (i < RPT - 1)
            load_row6(img, r + 2, c4, lane, nxt);

        float o[4];
        #pragma unroll
        for (int j = 0; j < 4; j++) {
            float gx = (top[j + 2] - top[j])
                     + 2.0f * (mid[j + 2] - mid[j])
                     + (bot[j + 2] - bot[j]);
            float gy = (bot[j]     - top[j])
                     + 2.0f * (bot[j + 1] - top[j + 1])
                     + (bot[j + 2] - top[j + 2]);
            o[j] = fabsf(gx) + fabsf(gy) + 1e-5f;
        }
        float4 ov = make_float4(o[0], o[1], o[2], o[3]);
        __stcs(reinterpret_cast<float4*>(op + (size_t)r * IMG_W + (size_t)c4 * 4), ov);

        #pragma unroll
        for (int k = 0; k < 6; k++) {
            top[k] = mid[k]; mid[k] = bot[k]; bot[k] = nxt[k];
        }
    }
}

extern "C" void kernel_launch(void* const* d_in, const int* in_sizes, int n_in,
                              void* d_out, int out_size) {
    const float* x = (const float*)d_in[0];
    float* out = (float*)d_out;

    int total_threads = out_size / (4 * RPT);     // 524288
    int blocks = (total_threads + 255) / 256;     // 2048
    sobel_grad_kernel<<<blocks, 256>>>(x, out);
}

// round 3
// speedup vs baseline: 1.1406x; 1.1352x over previous
#include <cuda_runtime.h>

// Sobel |gx|+|gy|+eps over (32,1,1024,1024) f32, SAME zero padding.
// Per-thread 4-wide x 16-tall strip. Raw float4 rows prefetched 2 iterations
// ahead (pure LDG, no dependent ops); shuffle-expansion to 6-wide window
// happens only at promotion time, keeping 2 wide loads in flight per thread.

#define IMG_W 1024
#define IMG_H 1024
#define C4    (IMG_W / 4)   // 256 float4 columns per row
#define RPT   16            // output rows per thread
#define RB    (IMG_H / RPT) // 64 row-blocks per image

struct RawRow {
    float4 c;
    float  l, r;   // only valid on lanes 0 / 31
};

__device__ __forceinline__ RawRow load_raw(const float* __restrict__ img,
                                           int r, int c4, int lane) {
    RawRow o;
    bool in = (unsigned)r < (unsigned)IMG_H;
    const float* base = img + (size_t)r * IMG_W + (size_t)c4 * 4;
    o.c = make_float4(0.f, 0.f, 0.f, 0.f);
    o.l = 0.f; o.r = 0.f;
    if (in) {
        o.c = *reinterpret_cast<const float4*>(base);
        if (lane == 0  && c4 > 0)      o.l = __ldg(base - 1);
        if (lane == 31 && c4 < C4 - 1) o.r = __ldg(base + 4);
    }
    return o;
}

__device__ __forceinline__ void expand(const RawRow& rr, int lane, float v[6]) {
    float left  = __shfl_up_sync(0xFFFFFFFFu, rr.c.w, 1);
    float right = __shfl_down_sync(0xFFFFFFFFu, rr.c.x, 1);
    if (lane == 0)  left  = rr.l;
    if (lane == 31) right = rr.r;
    v[0] = left;
    v[1] = rr.c.x; v[2] = rr.c.y; v[3] = rr.c.z; v[4] = rr.c.w;
    v[5] = right;
}

__global__ void __launch_bounds__(256)
sobel_grad_kernel(const float* __restrict__ x, float* __restrict__ out) {
    int idx  = blockIdx.x * blockDim.x + threadIdx.x;
    int lane = threadIdx.x & 31;
    int c4 = idx & (C4 - 1);          // float4 column  (0..255)
    int t  = idx >> 8;
    int rb = t & (RB - 1);            // row block      (0..63)
    int n  = t >> 6;                  // image index    (0..31)

    const float* img = x   + (size_t)n * IMG_H * IMG_W;
    float*       op  = out + (size_t)n * IMG_H * IMG_W;
    int row0 = rb * RPT;

    float top[6], mid[6], bot[6];
    RawRow praw;

    // Prologue: expand rows row0-1 .. row0+1, raw-prefetch row0+2.
    {
        RawRow r0 = load_raw(img, row0 - 1, c4, lane);
        RawRow r1 = load_raw(img, row0,     c4, lane);
        RawRow r2 = load_raw(img, row0 + 1, c4, lane);
        praw      = load_raw(img, row0 + 2, c4, lane);
        expand(r0, lane, top);
        expand(r1, lane, mid);
        expand(r2, lane, bot);
    }

    #pragma unroll
    for (int i = 0; i < RPT; i++) {
        int r = row0 + i;

        // Prefetch raw row r+3 (consumed 2 iterations later).
        RawRow nraw;
        if (i < RPT - 2)
            nraw = load_raw(img, r + 3, c4, lane);

        float o[4];
        #pragma unroll
        for (int j = 0; j < 4; j++) {
            float gx = (top[j + 2] - top[j])
                     + 2.0f * (mid[j + 2] - mid[j])
                     + (bot[j + 2] - bot[j]);
            float gy = (bot[j]     - top[j])
                     + 2.0f * (bot[j + 1] - top[j + 1])
                     + (bot[j + 2] - top[j + 2]);
            o[j] = fabsf(gx) + fabsf(gy) + 1e-5f;
        }
        float4 ov = make_float4(o[0], o[1], o[2], o[3]);
        __stcs(reinterpret_cast<float4*>(op + (size_t)r * IMG_W + (size_t)c4 * 4), ov);

        if (i < RPT - 1) {
            // Promote: shift window up, expand the prefetched row into bot.
            #pragma unroll
            for (int k = 0; k < 6; k++) { top[k] = mid[k]; mid[k] = bot[k]; }
            expand(praw, lane, bot);
            praw = nraw;
        }
    }
}

extern "C" void kernel_launch(void* const* d_in, const int* in_sizes, int n_in,
                              void* d_out, int out_size) {
    const float* x = (const float*)d_in[0];
    float* out = (float*)d_out;

    int total_threads = out_size / (4 * RPT);     // 524288
    int blocks = (total_threads + 255) / 256;     // 2048
    sobel_grad_kernel<<<blocks, 256>>>(x, out);
}